// round 4
// baseline (speedup 1.0000x reference)
#include <cuda_runtime.h>
#include <cstdint>

#define DI __device__ __forceinline__

__device__ float g_Q[4][4096];
__device__ float g_B1[4096];   // B1[r][j] = m_right[j][r]  (K-major)
__device__ float g_B2[4096];   // B2[l][i] = m_left[i][l]   (K-major)

DI uint32_t f2tf(float f) {
    uint32_t u;
    asm("cvt.rna.tf32.f32 %0, %1;" : "=r"(u) : "f"(f));
    return u;
}

DI void mma8(float& c0, float& c1, float& c2, float& c3,
             uint32_t a0, uint32_t a1, uint32_t a2, uint32_t a3,
             uint32_t b0, uint32_t b1) {
    asm volatile(
        "mma.sync.aligned.m16n8k8.row.col.f32.tf32.tf32.f32 "
        "{%0,%1,%2,%3}, {%4,%5,%6,%7}, {%8,%9}, {%0,%1,%2,%3};"
        : "+f"(c0), "+f"(c1), "+f"(c2), "+f"(c3)
        : "r"(a0), "r"(a1), "r"(a2), "r"(a3), "r"(b0), "r"(b1));
}

static constexpr int LD = 68;                      // floats; conflict-free stride
static constexpr uint32_t OFF_X  = 0;              // [128][68]
static constexpr uint32_t OFF_T  = 128 * LD;       // [128][68]
static constexpr uint32_t OFF_B1 = 2 * 128 * LD;   // [64][68]
static constexpr uint32_t OFF_B2 = OFF_B1 + 64 * LD;
static constexpr uint32_t SMEM_WORDS = OFF_B2 + 64 * LD;   // 26112 words
static constexpr uint32_t SMEM_BYTES = SMEM_WORDS * 4;     // 104448 B

// ---- Cayley: Q = (I - A/2)^-1 (I + A/2), Gauss-Jordan (no pivoting) ----
__global__ void cayley_kernel(const float* __restrict__ uL, const float* __restrict__ vL,
                              const float* __restrict__ uR, const float* __restrict__ vR) {
    __shared__ float Mat[64][64], Rhs[64][64], sf[64];
    __shared__ float pinv;
    const float* X = (blockIdx.x == 0) ? uL : (blockIdx.x == 1) ? vL
                   : (blockIdx.x == 2) ? uR : vR;
    int tid = threadIdx.x;
    for (int idx = tid; idx < 4096; idx += blockDim.x) {
        int i = idx >> 6, j = idx & 63;
        float a = (i > j) ? X[i * 64 + j] : (j > i) ? -X[j * 64 + i] : 0.f;
        float h = 0.5f * a, d = (i == j) ? 1.f : 0.f;
        Mat[i][j] = d - h;
        Rhs[i][j] = d + h;
    }
    __syncthreads();
    for (int k = 0; k < 64; k++) {
        if (tid == 0) pinv = 1.f / Mat[k][k];
        __syncthreads();
        if (tid < 64)       Mat[k][tid] *= pinv;
        else if (tid < 128) Rhs[k][tid - 64] *= pinv;
        else if (tid < 192) { int r = tid - 128; sf[r] = (r == k) ? 0.f : Mat[r][k]; }
        __syncthreads();
        for (int idx = tid; idx < 8192; idx += blockDim.x) {
            int r = idx >> 7, c = idx & 127;
            if (r == k) continue;
            float f = sf[r];
            if (c < 64) Mat[r][c] = fmaf(-f, Mat[k][c], Mat[r][c]);
            else { int cc = c - 64; Rhs[r][cc] = fmaf(-f, Rhs[k][cc], Rhs[r][cc]); }
        }
        __syncthreads();
    }
    for (int idx = tid; idx < 4096; idx += blockDim.x)
        g_Q[blockIdx.x][idx] = Rhs[idx >> 6][idx & 63];
}

// ---- combine: m = Cu @ diag(d) @ Cv ; store m^T (K-major rows) ----
__global__ void combine_kernel(const float* __restrict__ dl, const float* __restrict__ dr) {
    __shared__ float Cu[64][64], dCv[64][64];
    int b = blockIdx.x;  // 0: left -> g_B2, 1: right -> g_B1
    int tid = threadIdx.x;
    const float* Qu = g_Q[b * 2 + 0];
    const float* Qv = g_Q[b * 2 + 1];
    const float* dg = b ? dr : dl;
    for (int idx = tid; idx < 4096; idx += blockDim.x) {
        int t = idx >> 6, c = idx & 63;
        Cu[t][c]  = Qu[idx];
        dCv[t][c] = dg[t] * Qv[idx];
    }
    __syncthreads();
    float* dst = b ? g_B1 : g_B2;
    for (int idx = tid; idx < 4096; idx += blockDim.x) {
        int i = idx >> 6, l = idx & 63;
        float acc = 0.f;
#pragma unroll 16
        for (int t = 0; t < 64; t++) acc = fmaf(Cu[i][t], dCv[t][l], acc);
        dst[l * 64 + i] = acc;   // row l, col i  => m^T, K-major
    }
}

// one warp computes C[32x32] tile of D[128(or 128)x64] = A(K-major) * B(K-major)^T
DI void warp_gemm(const uint32_t* __restrict__ sA, const uint32_t* __restrict__ sB,
                  float c[2][4][4], int rbase, int cbase, int lane) {
    int ar = lane >> 2, ac = lane & 3;
#pragma unroll
    for (int k = 0; k < 8; k++) {
        uint32_t a[2][4];
#pragma unroll
        for (int m = 0; m < 2; m++) {
            const uint32_t* p = sA + (rbase + 16 * m + ar) * LD + 8 * k + ac;
            a[m][0] = p[0];
            a[m][1] = p[8 * LD];
            a[m][2] = p[4];
            a[m][3] = p[8 * LD + 4];
        }
#pragma unroll
        for (int n = 0; n < 4; n++) {
            const uint32_t* q = sB + (cbase + 8 * n + ar) * LD + 8 * k + ac;
            uint32_t b0 = q[0], b1 = q[4];
#pragma unroll
            for (int m = 0; m < 2; m++)
                mma8(c[m][n][0], c[m][n][1], c[m][n][2], c[m][n][3],
                     a[m][0], a[m][1], a[m][2], a[m][3], b0, b1);
        }
    }
}

__global__ void __launch_bounds__(256, 2)
kron_kernel(const float* __restrict__ x, const float* __restrict__ ds,
            float* __restrict__ out, int n_tiles) {
    extern __shared__ uint32_t sm[];
    uint32_t* sX  = sm + OFF_X;
    uint32_t* sT  = sm + OFF_T;
    uint32_t* sB1 = sm + OFF_B1;
    uint32_t* sB2 = sm + OFF_B2;
    int tid = threadIdx.x, lane = tid & 31, w = tid >> 5;
    int wr = w & 3, wc = w >> 2;
    int rbase = 32 * wr, cbase = 32 * wc;

    for (int idx = tid; idx < 4096; idx += 256) {
        int r = idx >> 6, cc = idx & 63;
        sB1[r * LD + cc] = f2tf(g_B1[idx]);
        sB2[r * LD + cc] = f2tf(g_B2[idx]);
    }
    // first __syncthreads (S1 of tile 0) orders these writes before use

    const float4* x4  = (const float4*)x;
    const float4* ds4 = (const float4*)ds;

    for (int tile = blockIdx.x; tile < n_tiles; tile += gridDim.x) {
        size_t base = (size_t)tile * 2048;  // float4 units (2 samples * 4096 f / 4)
#pragma unroll
        for (int it = 0; it < 8; it++) {
            int q = tid + it * 256;
            float4 v = x4[base + q];
            float4 s = ds4[q & 1023];
            uint4 u;
            u.x = f2tf(v.x * s.x); u.y = f2tf(v.y * s.y);
            u.z = f2tf(v.z * s.z); u.w = f2tf(v.w * s.w);
            int e = q << 2, n = e >> 12, h = e & 4095;
            *(uint4*)(sX + ((n << 6) + (h >> 6)) * LD + (h & 63)) = u;
        }
        __syncthreads();   // S1

        float c[2][4][4];
#pragma unroll
        for (int m = 0; m < 2; m++)
#pragma unroll
            for (int n = 0; n < 4; n++)
#pragma unroll
                for (int i = 0; i < 4; i++) c[m][n][i] = 0.f;

        warp_gemm(sX, sB1, c, rbase, cbase, lane);   // T[(n,i),r]

        {   // store C1 transposed into sT: (row=(n,i), col=r) -> sT[(n,r)][i]
            int ar = lane >> 2, bc = lane & 3;
#pragma unroll
            for (int m = 0; m < 2; m++) {
#pragma unroll
                for (int n = 0; n < 4; n++) {
                    int R0 = rbase + 16 * m + ar;     // (nloc*64 + i)
                    int r0 = cbase + 8 * n + 2 * bc;  // r
                    int nl = R0 & 64;                 // sample bit
                    int i0 = R0 & 63;
                    sT[(nl + r0)     * LD + i0]     = f2tf(c[m][n][0]);
                    sT[(nl + r0 + 1) * LD + i0]     = f2tf(c[m][n][1]);
                    sT[(nl + r0)     * LD + i0 + 8] = f2tf(c[m][n][2]);
                    sT[(nl + r0 + 1) * LD + i0 + 8] = f2tf(c[m][n][3]);
                }
            }
        }
        __syncthreads();   // S2

#pragma unroll
        for (int m = 0; m < 2; m++)
#pragma unroll
            for (int n = 0; n < 4; n++)
#pragma unroll
                for (int i = 0; i < 4; i++) c[m][n][i] = 0.f;

        warp_gemm(sT, sB2, c, rbase, cbase, lane);   // out^T[(n,r), l]

        {   // C2 (row=(n,r), col=l) -> out[2*tile+n][l][r]
            int ar = lane >> 2, bc = lane & 3;
            float* ob = out + (size_t)tile * 8192;
#pragma unroll
            for (int m = 0; m < 2; m++) {
#pragma unroll
                for (int n = 0; n < 4; n++) {
                    int R0 = rbase + 16 * m + ar;
                    int l0 = cbase + 8 * n + 2 * bc;
                    float* p = ob + (R0 >> 6) * 4096 + (R0 & 63);
                    p[l0 * 64]           = c[m][n][0];
                    p[(l0 + 1) * 64]     = c[m][n][1];
                    p[l0 * 64 + 8]       = c[m][n][2];
                    p[(l0 + 1) * 64 + 8] = c[m][n][3];
                }
            }
        }
        // no extra barrier needed: next iter's S1 orders new sX writes
        // after every warp's sT reads, and S2 orders new sT writes after sX reads.
    }
}

extern "C" void kernel_launch(void* const* d_in, const int* in_sizes, int n_in,
                              void* d_out, int out_size) {
    const float* x  = (const float*)d_in[0];
    const float* uL = (const float*)d_in[1];
    const float* vL = (const float*)d_in[2];
    const float* dL = (const float*)d_in[3];
    const float* uR = (const float*)d_in[4];
    const float* vR = (const float*)d_in[5];
    const float* dR = (const float*)d_in[6];
    const float* ds = (const float*)d_in[7];
    float* out = (float*)d_out;

    int n_samples = in_sizes[0] / 4096;
    int n_tiles = n_samples / 2;

    cudaFuncSetAttribute(kron_kernel, cudaFuncAttributeMaxDynamicSharedMemorySize,
                         SMEM_BYTES);

    cayley_kernel<<<4, 256>>>(uL, vL, uR, vR);
    combine_kernel<<<2, 256>>>(dL, dR);

    int grid = n_tiles < 304 ? n_tiles : 304;
    kron_kernel<<<grid, 256, SMEM_BYTES>>>(x, ds, out, n_tiles);
}

// round 5
// speedup vs baseline: 3.4481x; 3.4481x over previous
#include <cuda_runtime.h>
#include <cstdint>

#define DI __device__ __forceinline__

__device__ float g_Q[4][4096];
__device__ float g_B1[4096];   // B1[r][j] = m_right[j][r]  (K-major)
__device__ float g_B2[4096];   // B2[l][i] = m_left[i][l]   (K-major)

DI uint32_t f2tf(float f) {
    uint32_t u;
    asm("cvt.rna.tf32.f32 %0, %1;" : "=r"(u) : "f"(f));
    return u;
}

DI void mma8(float& c0, float& c1, float& c2, float& c3,
             uint32_t a0, uint32_t a1, uint32_t a2, uint32_t a3,
             uint32_t b0, uint32_t b1) {
    asm volatile(
        "mma.sync.aligned.m16n8k8.row.col.f32.tf32.tf32.f32 "
        "{%0,%1,%2,%3}, {%4,%5,%6,%7}, {%8,%9}, {%0,%1,%2,%3};"
        : "+f"(c0), "+f"(c1), "+f"(c2), "+f"(c3)
        : "r"(a0), "r"(a1), "r"(a2), "r"(a3), "r"(b0), "r"(b1));
}

static constexpr int LD = 68;
static constexpr uint32_t OFF_X  = 0;
static constexpr uint32_t OFF_T  = 128 * LD;
static constexpr uint32_t OFF_B1 = 2 * 128 * LD;
static constexpr uint32_t OFF_B2 = OFF_B1 + 64 * LD;
static constexpr uint32_t SMEM_WORDS = OFF_B2 + 64 * LD;
static constexpr uint32_t SMEM_BYTES = SMEM_WORDS * 4;          // 104448 B

// Cayley scratch: 4 buffers [64][68]
static constexpr uint32_t CAY_BYTES = 4 * 64 * LD * 4;          // 69632 B

// ---- fast 64x64x64 matmul, 256 threads, fp32: C = A*B ----
DI void mm64(float* __restrict__ C, const float* __restrict__ A,
             const float* __restrict__ B, int ty, int tx) {
    float acc[4][4];
#pragma unroll
    for (int m = 0; m < 4; m++)
#pragma unroll
        for (int n = 0; n < 4; n++) acc[m][n] = 0.f;
#pragma unroll 4
    for (int k = 0; k < 64; k++) {
        float a0 = A[(4 * ty + 0) * LD + k];
        float a1 = A[(4 * ty + 1) * LD + k];
        float a2 = A[(4 * ty + 2) * LD + k];
        float a3 = A[(4 * ty + 3) * LD + k];
        float4 b = *(const float4*)&B[k * LD + 4 * tx];
        acc[0][0] = fmaf(a0, b.x, acc[0][0]); acc[0][1] = fmaf(a0, b.y, acc[0][1]);
        acc[0][2] = fmaf(a0, b.z, acc[0][2]); acc[0][3] = fmaf(a0, b.w, acc[0][3]);
        acc[1][0] = fmaf(a1, b.x, acc[1][0]); acc[1][1] = fmaf(a1, b.y, acc[1][1]);
        acc[1][2] = fmaf(a1, b.z, acc[1][2]); acc[1][3] = fmaf(a1, b.w, acc[1][3]);
        acc[2][0] = fmaf(a2, b.x, acc[2][0]); acc[2][1] = fmaf(a2, b.y, acc[2][1]);
        acc[2][2] = fmaf(a2, b.z, acc[2][2]); acc[2][3] = fmaf(a2, b.w, acc[2][3]);
        acc[3][0] = fmaf(a3, b.x, acc[3][0]); acc[3][1] = fmaf(a3, b.y, acc[3][1]);
        acc[3][2] = fmaf(a3, b.z, acc[3][2]); acc[3][3] = fmaf(a3, b.w, acc[3][3]);
    }
    __syncthreads();
#pragma unroll
    for (int m = 0; m < 4; m++) {
        float4 v = make_float4(acc[m][0], acc[m][1], acc[m][2], acc[m][3]);
        *(float4*)&C[(4 * ty + m) * LD + 4 * tx] = v;
    }
    __syncthreads();
}

// ---- Cayley via exact product expansion:
//  Q = (I-M)^-1 (I+M) = (I+M)^2 (I+M^2)(I+M^4)(I+M^8)  (+O(||M||^16), ~1e-13)
__global__ void cayley_kernel(const float* __restrict__ uL, const float* __restrict__ vL,
                              const float* __restrict__ uR, const float* __restrict__ vR) {
    extern __shared__ float cs[];
    float* B0 = cs;                 // M, later M^4
    float* B1 = cs + 64 * LD;       // P (running product)
    float* B2 = cs + 2 * 64 * LD;   // M^2, later M^8
    float* B3 = cs + 3 * 64 * LD;   // temp products
    const float* X = (blockIdx.x == 0) ? uL : (blockIdx.x == 1) ? vL
                   : (blockIdx.x == 2) ? uR : vR;
    int tid = threadIdx.x, ty = tid >> 4, tx = tid & 15;

    for (int idx = tid; idx < 4096; idx += 256) {
        int i = idx >> 6, j = idx & 63;
        float a = (i > j) ? X[i * 64 + j] : (j > i) ? -X[j * 64 + i] : 0.f;
        float m = 0.5f * a;
        B0[i * LD + j] = m;
        B1[i * LD + j] = ((i == j) ? 1.f : 0.f) + 2.f * m;   // I + 2M
    }
    __syncthreads();
    mm64(B2, B0, B0, ty, tx);                                // B2 = M^2
    for (int idx = tid; idx < 4096; idx += 256) {            // P = (I+M)^2
        int i = idx >> 6, j = idx & 63;
        B1[i * LD + j] += B2[i * LD + j];
    }
    __syncthreads();
    mm64(B3, B1, B2, ty, tx);                                // B3 = P*M^2
    for (int idx = tid; idx < 4096; idx += 256) {            // P *= (I+M^2)
        int i = idx >> 6, j = idx & 63;
        B1[i * LD + j] += B3[i * LD + j];
    }
    __syncthreads();
    mm64(B0, B2, B2, ty, tx);                                // B0 = M^4  (M dead)
    mm64(B3, B1, B0, ty, tx);                                // B3 = P*M^4
    for (int idx = tid; idx < 4096; idx += 256) {
        int i = idx >> 6, j = idx & 63;
        B1[i * LD + j] += B3[i * LD + j];                    // P *= (I+M^4)
    }
    __syncthreads();
    mm64(B2, B0, B0, ty, tx);                                // B2 = M^8
    mm64(B3, B1, B2, ty, tx);                                // B3 = P*M^8
    for (int idx = tid; idx < 4096; idx += 256) {
        int i = idx >> 6, j = idx & 63;
        g_Q[blockIdx.x][idx] = B1[i * LD + j] + B3[i * LD + j];   // Q
    }
}

// ---- combine: m = Cu @ diag(d) @ Cv ; store m^T (K-major rows) ----
__global__ void combine_kernel(const float* __restrict__ dl, const float* __restrict__ dr) {
    __shared__ float Cu[64][64], dCv[64][64];
    int b = blockIdx.x;  // 0: left -> g_B2, 1: right -> g_B1
    int tid = threadIdx.x;
    const float* Qu = g_Q[b * 2 + 0];
    const float* Qv = g_Q[b * 2 + 1];
    const float* dg = b ? dr : dl;
    for (int idx = tid; idx < 4096; idx += blockDim.x) {
        int t = idx >> 6, c = idx & 63;
        Cu[t][c]  = Qu[idx];
        dCv[t][c] = dg[t] * Qv[idx];
    }
    __syncthreads();
    float* dst = b ? g_B1 : g_B2;
    for (int idx = tid; idx < 4096; idx += blockDim.x) {
        int i = idx >> 6, l = idx & 63;
        float acc = 0.f;
#pragma unroll 16
        for (int t = 0; t < 64; t++) acc = fmaf(Cu[i][t], dCv[t][l], acc);
        dst[l * 64 + i] = acc;   // row l, col i  => m^T, K-major
    }
}

// one warp computes C[32x32] tile of D = A(K-major) * B(K-major)^T
DI void warp_gemm(const uint32_t* __restrict__ sA, const uint32_t* __restrict__ sB,
                  float c[2][4][4], int rbase, int cbase, int lane) {
    int ar = lane >> 2, ac = lane & 3;
#pragma unroll
    for (int k = 0; k < 8; k++) {
        uint32_t a[2][4];
#pragma unroll
        for (int m = 0; m < 2; m++) {
            const uint32_t* p = sA + (rbase + 16 * m + ar) * LD + 8 * k + ac;
            a[m][0] = p[0];
            a[m][1] = p[8 * LD];
            a[m][2] = p[4];
            a[m][3] = p[8 * LD + 4];
        }
#pragma unroll
        for (int n = 0; n < 4; n++) {
            const uint32_t* q = sB + (cbase + 8 * n + ar) * LD + 8 * k + ac;
            uint32_t b0 = q[0], b1 = q[4];
#pragma unroll
            for (int m = 0; m < 2; m++)
                mma8(c[m][n][0], c[m][n][1], c[m][n][2], c[m][n][3],
                     a[m][0], a[m][1], a[m][2], a[m][3], b0, b1);
        }
    }
}

__global__ void __launch_bounds__(256, 2)
kron_kernel(const float* __restrict__ x, const float* __restrict__ ds,
            float* __restrict__ out, int n_tiles) {
    extern __shared__ uint32_t sm[];
    uint32_t* sX  = sm + OFF_X;
    uint32_t* sT  = sm + OFF_T;
    uint32_t* sB1 = sm + OFF_B1;
    uint32_t* sB2 = sm + OFF_B2;
    int tid = threadIdx.x, lane = tid & 31, w = tid >> 5;
    int wr = w & 3, wc = w >> 2;
    int rbase = 32 * wr, cbase = 32 * wc;

    for (int idx = tid; idx < 4096; idx += 256) {
        int r = idx >> 6, cc = idx & 63;
        sB1[r * LD + cc] = f2tf(g_B1[idx]);
        sB2[r * LD + cc] = f2tf(g_B2[idx]);
    }

    const float4* x4  = (const float4*)x;
    const float4* ds4 = (const float4*)ds;

    for (int tile = blockIdx.x; tile < n_tiles; tile += gridDim.x) {
        size_t base = (size_t)tile * 2048;
#pragma unroll
        for (int it = 0; it < 8; it++) {
            int q = tid + it * 256;
            float4 v = x4[base + q];
            float4 s = ds4[q & 1023];
            uint4 u;
            u.x = f2tf(v.x * s.x); u.y = f2tf(v.y * s.y);
            u.z = f2tf(v.z * s.z); u.w = f2tf(v.w * s.w);
            int e = q << 2, n = e >> 12, h = e & 4095;
            *(uint4*)(sX + ((n << 6) + (h >> 6)) * LD + (h & 63)) = u;
        }
        __syncthreads();   // S1

        float c[2][4][4];
#pragma unroll
        for (int m = 0; m < 2; m++)
#pragma unroll
            for (int n = 0; n < 4; n++)
#pragma unroll
                for (int i = 0; i < 4; i++) c[m][n][i] = 0.f;

        warp_gemm(sX, sB1, c, rbase, cbase, lane);   // T[(n,i),r]

        {
            int ar = lane >> 2, bc = lane & 3;
#pragma unroll
            for (int m = 0; m < 2; m++) {
#pragma unroll
                for (int n = 0; n < 4; n++) {
                    int R0 = rbase + 16 * m + ar;
                    int r0 = cbase + 8 * n + 2 * bc;
                    int nl = R0 & 64;
                    int i0 = R0 & 63;
                    sT[(nl + r0)     * LD + i0]     = f2tf(c[m][n][0]);
                    sT[(nl + r0 + 1) * LD + i0]     = f2tf(c[m][n][1]);
                    sT[(nl + r0)     * LD + i0 + 8] = f2tf(c[m][n][2]);
                    sT[(nl + r0 + 1) * LD + i0 + 8] = f2tf(c[m][n][3]);
                }
            }
        }
        __syncthreads();   // S2

#pragma unroll
        for (int m = 0; m < 2; m++)
#pragma unroll
            for (int n = 0; n < 4; n++)
#pragma unroll
                for (int i = 0; i < 4; i++) c[m][n][i] = 0.f;

        warp_gemm(sT, sB2, c, rbase, cbase, lane);   // out^T[(n,r), l]

        {
            int ar = lane >> 2, bc = lane & 3;
            float* ob = out + (size_t)tile * 8192;
#pragma unroll
            for (int m = 0; m < 2; m++) {
#pragma unroll
                for (int n = 0; n < 4; n++) {
                    int R0 = rbase + 16 * m + ar;
                    int l0 = cbase + 8 * n + 2 * bc;
                    float* p = ob + (R0 >> 6) * 4096 + (R0 & 63);
                    p[l0 * 64]           = c[m][n][0];
                    p[(l0 + 1) * 64]     = c[m][n][1];
                    p[l0 * 64 + 8]       = c[m][n][2];
                    p[(l0 + 1) * 64 + 8] = c[m][n][3];
                }
            }
        }
    }
}

extern "C" void kernel_launch(void* const* d_in, const int* in_sizes, int n_in,
                              void* d_out, int out_size) {
    const float* x  = (const float*)d_in[0];
    const float* uL = (const float*)d_in[1];
    const float* vL = (const float*)d_in[2];
    const float* dL = (const float*)d_in[3];
    const float* uR = (const float*)d_in[4];
    const float* vR = (const float*)d_in[5];
    const float* dR = (const float*)d_in[6];
    const float* ds = (const float*)d_in[7];
    float* out = (float*)d_out;

    int n_samples = in_sizes[0] / 4096;
    int n_tiles = n_samples / 2;

    cudaFuncSetAttribute(kron_kernel, cudaFuncAttributeMaxDynamicSharedMemorySize,
                         SMEM_BYTES);
    cudaFuncSetAttribute(cayley_kernel, cudaFuncAttributeMaxDynamicSharedMemorySize,
                         CAY_BYTES);

    cayley_kernel<<<4, 256, CAY_BYTES>>>(uL, vL, uR, vR);
    combine_kernel<<<2, 256>>>(dL, dR);

    int grid = n_tiles < 296 ? n_tiles : 296;
    kron_kernel<<<grid, 256, SMEM_BYTES>>>(x, ds, out, n_tiles);
}